// round 1
// baseline (speedup 1.0000x reference)
#include <cuda_runtime.h>
#include <cuda_bf16.h>
#include <math.h>

#define Bdim 2
#define Ldim 2048
#define Ddim 1024
#define Hdim 16
#define DKdim 64
#define INNERdim 1024
#define Mdim (Bdim*Ldim)   // 4096

// Scratch (no allocations allowed)
__device__ float g_q[Bdim*Hdim*Ldim*DKdim];
__device__ float g_k[Bdim*Hdim*Ldim*DKdim];
__device__ float g_v[Bdim*Hdim*Ldim*DKdim];
__device__ float g_ctx[Bdim*Ldim*INNERdim];

// ---------------------------------------------------------------------------
// Tiled fp32 GEMM: out[M,N] = A[M,K] @ W[K,N] + bias[N]
// M=4096, N=1024, K=1024 hardcoded. Tile 64x64, BK=16, 256 threads, 4x4 micro.
// LAYOUT 0: plain row-major [M,N]
// LAYOUT 1: scatter to [b, h, l, dk]  (QKV head-major layout)
// ---------------------------------------------------------------------------
template<int LAYOUT>
__global__ void proj_kernel(const float* __restrict__ A,
                            const float* __restrict__ W,
                            const float* __restrict__ bias,
                            float* __restrict__ out)
{
    __shared__ float As[64][17];
    __shared__ float Bs[16][64];

    const int tid = threadIdx.x;
    const int tx = tid & 15;          // 0..15
    const int ty = tid >> 4;          // 0..15
    const int m0 = blockIdx.y * 64;
    const int n0 = blockIdx.x * 64;

    const int ar = tid >> 2;          // 0..63   A tile row
    const int ac = (tid & 3) * 4;     // 0..12   A tile col (float4)
    const int br = tid >> 4;          // 0..15   B tile row
    const int bc = (tid & 15) * 4;    // 0..60   B tile col (float4)

    float acc[4][4] = {};

    for (int k0 = 0; k0 < 1024; k0 += 16) {
        float4 a4 = *(const float4*)(A + (size_t)(m0 + ar) * 1024 + k0 + ac);
        As[ar][ac]   = a4.x; As[ar][ac+1] = a4.y;
        As[ar][ac+2] = a4.z; As[ar][ac+3] = a4.w;
        float4 b4 = *(const float4*)(W + (size_t)(k0 + br) * 1024 + n0 + bc);
        *(float4*)(&Bs[br][bc]) = b4;
        __syncthreads();

        #pragma unroll
        for (int kk = 0; kk < 16; kk++) {
            float a[4], b[4];
            #pragma unroll
            for (int i = 0; i < 4; i++) a[i] = As[ty + i*16][kk];
            float4 bb = *(float4*)(&Bs[kk][tx*4]);
            b[0] = bb.x; b[1] = bb.y; b[2] = bb.z; b[3] = bb.w;
            #pragma unroll
            for (int i = 0; i < 4; i++)
                #pragma unroll
                for (int j = 0; j < 4; j++)
                    acc[i][j] = fmaf(a[i], b[j], acc[i][j]);
        }
        __syncthreads();
    }

    #pragma unroll
    for (int i = 0; i < 4; i++) {
        const int m = m0 + ty + i*16;
        const int nbase = n0 + tx*4;
        float4 o;
        o.x = acc[i][0] + bias[nbase+0];
        o.y = acc[i][1] + bias[nbase+1];
        o.z = acc[i][2] + bias[nbase+2];
        o.w = acc[i][3] + bias[nbase+3];
        if (LAYOUT == 0) {
            *(float4*)(out + (size_t)m * 1024 + nbase) = o;
        } else {
            const int b  = m >> 11;       // / 2048
            const int l  = m & 2047;
            const int h  = nbase >> 6;    // / 64  (all 4 cols same head)
            const int dk = nbase & 63;
            *(float4*)(out + (((size_t)(b*Hdim + h) * Ldim) + l) * DKdim + dk) = o;
        }
    }
}

// ---------------------------------------------------------------------------
// Flash attention: one CTA per (b, h, 64-query tile). 256 threads.
// Dynamic smem: Qs[64][65], Ks[64][65], Ss[64][65], Vs[64][68], m/l/c[64]
// ---------------------------------------------------------------------------
#define SMEM_FLOATS (3*64*65 + 64*68 + 192)
#define SMEM_BYTES  (SMEM_FLOATS * 4)

__global__ void attn_kernel(const float* __restrict__ Qg,
                            const float* __restrict__ Kg,
                            const float* __restrict__ Vg,
                            float* __restrict__ ctx)
{
    extern __shared__ float sm[];
    float (*Qs)[65] = (float(*)[65])(sm);
    float (*Ks)[65] = (float(*)[65])(sm + 64*65);
    float (*Vs)[68] = (float(*)[68])(sm + 2*64*65);
    float (*Ss)[65] = (float(*)[65])(sm + 2*64*65 + 64*68);
    float* mrow = sm + 3*64*65 + 64*68;
    float* lrow = mrow + 64;
    float* crow = lrow + 64;

    const int tid = threadIdx.x;
    const int tx = tid & 15;
    const int ty = tid >> 4;
    const int qb = blockIdx.x * 64;
    const int h  = blockIdx.y;
    const int b  = blockIdx.z;
    const float scale = 0.125f;   // 1/sqrt(64)

    const size_t hoff = ((size_t)(b*Hdim + h)) * Ldim * DKdim;
    const float* Qh = Qg + hoff;
    const float* Kh = Kg + hoff;
    const float* Vh = Vg + hoff;

    // Load Q tile (pre-scaled)
    for (int i = tid; i < 64*16; i += 256) {
        int r = i >> 4, c = (i & 15) * 4;
        float4 v = *(const float4*)(Qh + (size_t)(qb + r) * 64 + c);
        Qs[r][c]   = v.x * scale; Qs[r][c+1] = v.y * scale;
        Qs[r][c+2] = v.z * scale; Qs[r][c+3] = v.w * scale;
    }
    if (tid < 64) { mrow[tid] = -1e30f; lrow[tid] = 0.0f; }

    float acc[4][4] = {};
    const int srow = tid >> 2;   // softmax row (0..63)
    const int ssub = tid & 3;    // quarter of the 64 columns

    for (int j = 0; j < Ldim; j += 64) {
        // Load K, V tiles
        for (int i = tid; i < 64*16; i += 256) {
            int r = i >> 4, c = (i & 15) * 4;
            float4 kv = *(const float4*)(Kh + (size_t)(j + r) * 64 + c);
            Ks[r][c]   = kv.x; Ks[r][c+1] = kv.y;
            Ks[r][c+2] = kv.z; Ks[r][c+3] = kv.w;
            float4 vv = *(const float4*)(Vh + (size_t)(j + r) * 64 + c);
            *(float4*)(&Vs[r][c]) = vv;
        }
        __syncthreads();

        // S = (Q*scale) @ K^T
        float s[4][4] = {};
        #pragma unroll
        for (int d = 0; d < 64; d++) {
            float a[4], bb[4];
            #pragma unroll
            for (int i = 0; i < 4; i++)  a[i]  = Qs[ty + i*16][d];
            #pragma unroll
            for (int jj = 0; jj < 4; jj++) bb[jj] = Ks[tx + jj*16][d];
            #pragma unroll
            for (int i = 0; i < 4; i++)
                #pragma unroll
                for (int jj = 0; jj < 4; jj++)
                    s[i][jj] = fmaf(a[i], bb[jj], s[i][jj]);
        }
        #pragma unroll
        for (int i = 0; i < 4; i++)
            #pragma unroll
            for (int jj = 0; jj < 4; jj++)
                Ss[ty + i*16][tx + jj*16] = s[i][jj];
        __syncthreads();

        // Online softmax update (4 lanes per row)
        float pm = -1e30f;
        #pragma unroll
        for (int c = 0; c < 16; c++) pm = fmaxf(pm, Ss[srow][ssub*16 + c]);
        pm = fmaxf(pm, __shfl_xor_sync(0xffffffffu, pm, 1));
        pm = fmaxf(pm, __shfl_xor_sync(0xffffffffu, pm, 2));
        const float mold = mrow[srow];
        const float mnew = fmaxf(mold, pm);
        float psum = 0.0f;
        #pragma unroll
        for (int c = 0; c < 16; c++) {
            float e = __expf(Ss[srow][ssub*16 + c] - mnew);
            Ss[srow][ssub*16 + c] = e;
            psum += e;
        }
        psum += __shfl_xor_sync(0xffffffffu, psum, 1);
        psum += __shfl_xor_sync(0xffffffffu, psum, 2);
        const float corr = __expf(mold - mnew);
        if (ssub == 0) {
            mrow[srow] = mnew;
            lrow[srow] = lrow[srow] * corr + psum;
            crow[srow] = corr;
        }
        __syncthreads();

        // O = O*corr + P @ V
        float cc[4];
        #pragma unroll
        for (int i = 0; i < 4; i++) cc[i] = crow[ty + i*16];
        #pragma unroll
        for (int i = 0; i < 4; i++)
            #pragma unroll
            for (int jj = 0; jj < 4; jj++)
                acc[i][jj] *= cc[i];
        #pragma unroll 8
        for (int k = 0; k < 64; k++) {
            float p[4];
            #pragma unroll
            for (int i = 0; i < 4; i++) p[i] = Ss[ty + i*16][k];
            float4 v4 = *(float4*)(&Vs[k][tx*4]);
            float vv[4] = {v4.x, v4.y, v4.z, v4.w};
            #pragma unroll
            for (int i = 0; i < 4; i++)
                #pragma unroll
                for (int jj = 0; jj < 4; jj++)
                    acc[i][jj] = fmaf(p[i], vv[jj], acc[i][jj]);
        }
        __syncthreads();
    }

    // Epilogue: normalize, write ctx[b, l, h*64 + d]
    #pragma unroll
    for (int i = 0; i < 4; i++) {
        const int r = ty + i*16;
        const float inv = 1.0f / lrow[r];
        const int l = qb + r;
        float4 o;
        o.x = acc[i][0] * inv; o.y = acc[i][1] * inv;
        o.z = acc[i][2] * inv; o.w = acc[i][3] * inv;
        *(float4*)(ctx + ((size_t)b * Ldim + l) * INNERdim + h*64 + tx*4) = o;
    }
}

// ---------------------------------------------------------------------------
extern "C" void kernel_launch(void* const* d_in, const int* in_sizes, int n_in,
                              void* d_out, int out_size)
{
    const float* x   = (const float*)d_in[0];
    const float* w_q = (const float*)d_in[1];
    const float* b_q = (const float*)d_in[2];
    const float* w_k = (const float*)d_in[3];
    const float* b_k = (const float*)d_in[4];
    const float* w_v = (const float*)d_in[5];
    const float* b_v = (const float*)d_in[6];
    const float* w_o = (const float*)d_in[7];
    const float* b_o = (const float*)d_in[8];

    float *gq, *gk, *gv, *gctx;
    cudaGetSymbolAddress((void**)&gq,   g_q);
    cudaGetSymbolAddress((void**)&gk,   g_k);
    cudaGetSymbolAddress((void**)&gv,   g_v);
    cudaGetSymbolAddress((void**)&gctx, g_ctx);

    cudaFuncSetAttribute(attn_kernel,
                         cudaFuncAttributeMaxDynamicSharedMemorySize, SMEM_BYTES);

    dim3 blk(256);
    dim3 gp(INNERdim/64, Mdim/64);   // (16, 64)

    proj_kernel<1><<<gp, blk>>>(x, w_q, b_q, gq);
    proj_kernel<1><<<gp, blk>>>(x, w_k, b_k, gk);
    proj_kernel<1><<<gp, blk>>>(x, w_v, b_v, gv);

    dim3 ga(Ldim/64, Hdim, Bdim);    // (32, 16, 2)
    attn_kernel<<<ga, blk, SMEM_BYTES>>>(gq, gk, gv, gctx);

    proj_kernel<0><<<gp, blk>>>(gctx, w_o, b_o, (float*)d_out);
}

// round 3
// speedup vs baseline: 2.8031x; 2.8031x over previous
#include <cuda_runtime.h>
#include <cstdint>
#include <math.h>

#define Bdim 2
#define Ldim 2048
#define Hdim 16
#define DKdim 64
#define INNERdim 1024
#define Mdim 4096          // B*L
#define Kdim 1024

// ---------------- scratch (no allocations allowed) ----------------
__device__ float g_q[Bdim*Hdim*Ldim*DKdim];
__device__ float g_k[Bdim*Hdim*Ldim*DKdim];
__device__ float g_v[Bdim*Hdim*Ldim*DKdim];
__device__ float g_ctx[Mdim*INNERdim];

// ---------------- tf32 mma helpers ----------------
__device__ __forceinline__ uint32_t f2tf(float f) {
    uint32_t u;
    asm("cvt.rna.tf32.f32 %0, %1;" : "=r"(u) : "f"(f));
    return u;
}
__device__ __forceinline__ void mma_tf32(float* d, const uint32_t* a, const uint32_t* b) {
    asm volatile(
        "mma.sync.aligned.m16n8k8.row.col.f32.tf32.tf32.f32 "
        "{%0,%1,%2,%3}, {%4,%5,%6,%7}, {%8,%9}, {%0,%1,%2,%3};"
        : "+f"(d[0]), "+f"(d[1]), "+f"(d[2]), "+f"(d[3])
        : "r"(a[0]), "r"(a[1]), "r"(a[2]), "r"(a[3]), "r"(b[0]), "r"(b[1]));
}

// ---------------------------------------------------------------------------
// tf32 tensor-core GEMM: out[M,N] = A[M,K] @ W[K,N] + bias,  M=4096,N=K=1024
// CTA tile 128x128, K-tile 32. 8 warps (2x4), warp tile 64x32.
// LAYOUT 0: row-major [M,1024].  LAYOUT 1: scatter to [b,h,l,dk].
// ---------------------------------------------------------------------------
template<int LAYOUT>
__global__ void __launch_bounds__(256, 2)
gemm_tf32_kernel(const float* __restrict__ A,
                 const float* __restrict__ W,
                 const float* __restrict__ bias,
                 float* __restrict__ out)
{
    __shared__ float As[128][36];   // 128 rows x 32 K (pad 4)
    __shared__ float Ws[32][136];   // 32 K rows x 128 N (pad 8)

    const int tid  = threadIdx.x;
    const int lane = tid & 31;
    const int wid  = tid >> 5;
    const int warpM = wid & 1;       // 0..1  -> 64 rows each
    const int warpN = wid >> 1;      // 0..3  -> 32 cols each
    const int mbase = warpM * 64;
    const int nbase = warpN * 32;
    const int m0 = blockIdx.y * 128;
    const int n0 = blockIdx.x * 128;
    const int lr = lane >> 2;        // 0..7
    const int lc = lane & 3;         // 0..3

    float acc[4][4][4] = {};

    for (int kt = 0; kt < 32; kt++) {
        const int k0 = kt * 32;
        // load A tile 128x32 (4 float4 per thread, 8 chunks/row)
        #pragma unroll
        for (int it = 0; it < 4; it++) {
            int ch = tid + it * 256;
            int r = ch >> 3, c4 = (ch & 7) * 4;
            float4 v = *(const float4*)(A + (size_t)(m0 + r) * Kdim + k0 + c4);
            *(float4*)(&As[r][c4]) = v;
        }
        // load W tile 32x128 (4 float4 per thread, 32 chunks/row)
        #pragma unroll
        for (int it = 0; it < 4; it++) {
            int ch = tid + it * 256;
            int r = ch >> 5, c4 = (ch & 31) * 4;
            float4 v = *(const float4*)(W + (size_t)(k0 + r) * 1024 + n0 + c4);
            *(float4*)(&Ws[r][c4]) = v;
        }
        __syncthreads();

        #pragma unroll
        for (int ks = 0; ks < 4; ks++) {
            const int kc = ks * 8;
            uint32_t af[4][4];
            #pragma unroll
            for (int mf = 0; mf < 4; mf++) {
                const int r0 = mbase + mf * 16 + lr;
                const int c0 = kc + lc;
                af[mf][0] = f2tf(As[r0][c0]);
                af[mf][1] = f2tf(As[r0 + 8][c0]);
                af[mf][2] = f2tf(As[r0][c0 + 4]);
                af[mf][3] = f2tf(As[r0 + 8][c0 + 4]);
            }
            uint32_t bf[4][2];
            #pragma unroll
            for (int nf = 0; nf < 4; nf++) {
                const int nn = nbase + nf * 8 + lr;
                bf[nf][0] = f2tf(Ws[kc + lc][nn]);
                bf[nf][1] = f2tf(Ws[kc + 4 + lc][nn]);
            }
            #pragma unroll
            for (int mf = 0; mf < 4; mf++)
                #pragma unroll
                for (int nf = 0; nf < 4; nf++)
                    mma_tf32(acc[mf][nf], af[mf], bf[nf]);
        }
        __syncthreads();
    }

    // epilogue
    #pragma unroll
    for (int mf = 0; mf < 4; mf++) {
        const int r0 = m0 + mbase + mf * 16 + lr;
        #pragma unroll
        for (int nf = 0; nf < 4; nf++) {
            const int n = n0 + nbase + nf * 8 + lc * 2;
            const float b0 = bias[n], b1 = bias[n + 1];
            float2 lo = make_float2(acc[mf][nf][0] + b0, acc[mf][nf][1] + b1);
            float2 hi = make_float2(acc[mf][nf][2] + b0, acc[mf][nf][3] + b1);
            if (LAYOUT == 0) {
                *(float2*)(out + (size_t)r0 * 1024 + n) = lo;
                *(float2*)(out + (size_t)(r0 + 8) * 1024 + n) = hi;
            } else {
                const int h = n >> 6, dk = n & 63;
                {
                    const int bb = r0 >> 11, l = r0 & 2047;
                    *(float2*)(out + (((size_t)(bb*Hdim + h) * Ldim) + l) * DKdim + dk) = lo;
                }
                {
                    const int m2 = r0 + 8;
                    const int bb = m2 >> 11, l = m2 & 2047;
                    *(float2*)(out + (((size_t)(bb*Hdim + h) * Ldim) + l) * DKdim + dk) = hi;
                }
            }
        }
    }
}

// ---------------------------------------------------------------------------
// Flash attention with tf32 mma for S = Q@K^T and O += P@V.
// One CTA per (b, h, 64-query tile). 256 threads, 8 warps (2x4).
// smem arrays stride 72 floats (conflict-free fragment access).
// ---------------------------------------------------------------------------
#define AST 72
#define SMEM_FLOATS (4*64*AST + 192)
#define SMEM_BYTES  (SMEM_FLOATS * 4)

__global__ void __launch_bounds__(256, 2)
attn_kernel(const float* __restrict__ Qg,
            const float* __restrict__ Kg,
            const float* __restrict__ Vg,
            float* __restrict__ ctx)
{
    extern __shared__ float sm[];
    float (*Qs)[AST] = (float(*)[AST])(sm);
    float (*Ks)[AST] = (float(*)[AST])(sm + 64*AST);
    float (*Vs)[AST] = (float(*)[AST])(sm + 2*64*AST);
    float (*Ss)[AST] = (float(*)[AST])(sm + 3*64*AST);
    float* mrow = sm + 4*64*AST;
    float* lrow = mrow + 64;
    float* crow = lrow + 64;

    const int tid  = threadIdx.x;
    const int lane = tid & 31;
    const int wid  = tid >> 5;
    const int warpM = wid & 1;     // 32 q-rows each
    const int warpN = wid >> 1;    // 16 cols each
    const int lr = lane >> 2, lc = lane & 3;
    const int qb = blockIdx.x * 64;
    const int h  = blockIdx.y;
    const int b  = blockIdx.z;
    const float scale = 0.125f;

    const size_t hoff = ((size_t)(b*Hdim + h)) * Ldim * DKdim;
    const float* Qh = Qg + hoff;
    const float* Kh = Kg + hoff;
    const float* Vh = Vg + hoff;

    // Load Q tile pre-scaled
    for (int i = tid; i < 64*16; i += 256) {
        int r = i >> 4, c = (i & 15) * 4;
        float4 v = *(const float4*)(Qh + (size_t)(qb + r) * 64 + c);
        Qs[r][c]   = v.x * scale; Qs[r][c+1] = v.y * scale;
        Qs[r][c+2] = v.z * scale; Qs[r][c+3] = v.w * scale;
    }
    if (tid < 64) { mrow[tid] = -1e30f; lrow[tid] = 0.0f; }

    float acc[2][2][4] = {};
    const int srow = tid >> 2;
    const int ssub = tid & 3;

    for (int j = 0; j < Ldim; j += 64) {
        for (int i = tid; i < 64*16; i += 256) {
            int r = i >> 4, c = (i & 15) * 4;
            float4 kv = *(const float4*)(Kh + (size_t)(j + r) * 64 + c);
            *(float4*)(&Ks[r][c]) = kv;
            float4 vv = *(const float4*)(Vh + (size_t)(j + r) * 64 + c);
            *(float4*)(&Vs[r][c]) = vv;
        }
        __syncthreads();

        // ---- S = Q @ K^T (tf32 mma) ----
        float s[2][2][4] = {};
        #pragma unroll
        for (int kk = 0; kk < 64; kk += 8) {
            uint32_t af[2][4];
            #pragma unroll
            for (int mf = 0; mf < 2; mf++) {
                const int r0 = warpM*32 + mf*16 + lr;
                const int c0 = kk + lc;
                af[mf][0] = f2tf(Qs[r0][c0]);
                af[mf][1] = f2tf(Qs[r0+8][c0]);
                af[mf][2] = f2tf(Qs[r0][c0+4]);
                af[mf][3] = f2tf(Qs[r0+8][c0+4]);
            }
            uint32_t bf[2][2];
            #pragma unroll
            for (int nf = 0; nf < 2; nf++) {
                const int nn = warpN*16 + nf*8 + lr;
                bf[nf][0] = f2tf(Ks[nn][kk + lc]);
                bf[nf][1] = f2tf(Ks[nn][kk + 4 + lc]);
            }
            #pragma unroll
            for (int mf = 0; mf < 2; mf++)
                #pragma unroll
                for (int nf = 0; nf < 2; nf++)
                    mma_tf32(s[mf][nf], af[mf], bf[nf]);
        }
        // store S fragments
        #pragma unroll
        for (int mf = 0; mf < 2; mf++) {
            const int r0 = warpM*32 + mf*16 + lr;
            #pragma unroll
            for (int nf = 0; nf < 2; nf++) {
                const int col = warpN*16 + nf*8 + lc*2;
                *(float2*)(&Ss[r0][col])     = make_float2(s[mf][nf][0], s[mf][nf][1]);
                *(float2*)(&Ss[r0+8][col])   = make_float2(s[mf][nf][2], s[mf][nf][3]);
            }
        }
        __syncthreads();

        // ---- online softmax (unchanged structure) ----
        float pm = -1e30f;
        #pragma unroll
        for (int c = 0; c < 16; c++) pm = fmaxf(pm, Ss[srow][ssub*16 + c]);
        pm = fmaxf(pm, __shfl_xor_sync(0xffffffffu, pm, 1));
        pm = fmaxf(pm, __shfl_xor_sync(0xffffffffu, pm, 2));
        const float mold = mrow[srow];
        const float mnew = fmaxf(mold, pm);
        float psum = 0.0f;
        #pragma unroll
        for (int c = 0; c < 16; c++) {
            float e = __expf(Ss[srow][ssub*16 + c] - mnew);
            Ss[srow][ssub*16 + c] = e;
            psum += e;
        }
        psum += __shfl_xor_sync(0xffffffffu, psum, 1);
        psum += __shfl_xor_sync(0xffffffffu, psum, 2);
        const float corr = __expf(mold - mnew);
        if (ssub == 0) {
            mrow[srow] = mnew;
            lrow[srow] = lrow[srow] * corr + psum;
            crow[srow] = corr;
        }
        __syncthreads();

        // ---- rescale acc, then O += P @ V (tf32 mma) ----
        #pragma unroll
        for (int mf = 0; mf < 2; mf++) {
            const int r0 = warpM*32 + mf*16 + lr;
            const float cl = crow[r0];
            const float chi = crow[r0 + 8];
            #pragma unroll
            for (int nf = 0; nf < 2; nf++) {
                acc[mf][nf][0] *= cl;  acc[mf][nf][1] *= cl;
                acc[mf][nf][2] *= chi; acc[mf][nf][3] *= chi;
            }
        }
        #pragma unroll
        for (int kk = 0; kk < 64; kk += 8) {
            uint32_t af[2][4];
            #pragma unroll
            for (int mf = 0; mf < 2; mf++) {
                const int r0 = warpM*32 + mf*16 + lr;
                const int c0 = kk + lc;
                af[mf][0] = f2tf(Ss[r0][c0]);
                af[mf][1] = f2tf(Ss[r0+8][c0]);
                af[mf][2] = f2tf(Ss[r0][c0+4]);
                af[mf][3] = f2tf(Ss[r0+8][c0+4]);
            }
            uint32_t bf[2][2];
            #pragma unroll
            for (int nf = 0; nf < 2; nf++) {
                const int nn = warpN*16 + nf*8 + lr;
                bf[nf][0] = f2tf(Vs[kk + lc][nn]);
                bf[nf][1] = f2tf(Vs[kk + 4 + lc][nn]);
            }
            #pragma unroll
            for (int mf = 0; mf < 2; mf++)
                #pragma unroll
                for (int nf = 0; nf < 2; nf++)
                    mma_tf32(acc[mf][nf], af[mf], bf[nf]);
        }
        __syncthreads();
    }

    // epilogue: normalize and write ctx[b, l, h*64 + dk]
    #pragma unroll
    for (int mf = 0; mf < 2; mf++) {
        const int r0 = warpM*32 + mf*16 + lr;
        const float inv_lo = 1.0f / lrow[r0];
        const float inv_hi = 1.0f / lrow[r0 + 8];
        #pragma unroll
        for (int nf = 0; nf < 2; nf++) {
            const int col = h*64 + warpN*16 + nf*8 + lc*2;
            {
                const int l = qb + r0;
                float2 o = make_float2(acc[mf][nf][0]*inv_lo, acc[mf][nf][1]*inv_lo);
                *(float2*)(ctx + ((size_t)b * Ldim + l) * INNERdim + col) = o;
            }
            {
                const int l = qb + r0 + 8;
                float2 o = make_float2(acc[mf][nf][2]*inv_hi, acc[mf][nf][3]*inv_hi);
                *(float2*)(ctx + ((size_t)b * Ldim + l) * INNERdim + col) = o;
            }
        }
    }
}

// ---------------------------------------------------------------------------
extern "C" void kernel_launch(void* const* d_in, const int* in_sizes, int n_in,
                              void* d_out, int out_size)
{
    const float* x   = (const float*)d_in[0];
    const float* w_q = (const float*)d_in[1];
    const float* b_q = (const float*)d_in[2];
    const float* w_k = (const float*)d_in[3];
    const float* b_k = (const float*)d_in[4];
    const float* w_v = (const float*)d_in[5];
    const float* b_v = (const float*)d_in[6];
    const float* w_o = (const float*)d_in[7];
    const float* b_o = (const float*)d_in[8];

    float *gq, *gk, *gv, *gctx;
    cudaGetSymbolAddress((void**)&gq,   g_q);
    cudaGetSymbolAddress((void**)&gk,   g_k);
    cudaGetSymbolAddress((void**)&gv,   g_v);
    cudaGetSymbolAddress((void**)&gctx, g_ctx);

    cudaFuncSetAttribute(attn_kernel,
                         cudaFuncAttributeMaxDynamicSharedMemorySize, SMEM_BYTES);

    dim3 blk(256);
    dim3 gg(INNERdim/128, Mdim/128);   // (8, 32)

    gemm_tf32_kernel<1><<<gg, blk>>>(x, w_q, b_q, gq);
    gemm_tf32_kernel<1><<<gg, blk>>>(x, w_k, b_k, gk);
    gemm_tf32_kernel<1><<<gg, blk>>>(x, w_v, b_v, gv);

    dim3 ga(Ldim/64, Hdim, Bdim);      // (32, 16, 2)
    attn_kernel<<<ga, blk, SMEM_BYTES>>>(gq, gk, gv, gctx);

    gemm_tf32_kernel<0><<<gg, blk>>>(gctx, w_o, b_o, (float*)d_out);
}

// round 4
// speedup vs baseline: 4.1754x; 1.4895x over previous
#include <cuda_runtime.h>
#include <cstdint>
#include <math.h>

#define Bdim 2
#define Ldim 2048
#define Hdim 16
#define DKdim 64
#define INNERdim 1024
#define Mdim 4096          // B*L
#define Kdim 1024

// ---------------- scratch (no allocations allowed) ----------------
__device__ float g_q[Bdim*Hdim*Ldim*DKdim];
__device__ float g_k[Bdim*Hdim*Ldim*DKdim];
__device__ float g_v[Bdim*Hdim*Ldim*DKdim];
__device__ float g_ctx[Mdim*INNERdim];

// ---------------- tf32 mma helpers ----------------
__device__ __forceinline__ uint32_t f2tf(float f) {
    uint32_t u;
    asm("cvt.rna.tf32.f32 %0, %1;" : "=r"(u) : "f"(f));
    return u;
}
__device__ __forceinline__ void mma_tf32(float* d, const uint32_t* a, const uint32_t* b) {
    asm volatile(
        "mma.sync.aligned.m16n8k8.row.col.f32.tf32.tf32.f32 "
        "{%0,%1,%2,%3}, {%4,%5,%6,%7}, {%8,%9}, {%0,%1,%2,%3};"
        : "+f"(d[0]), "+f"(d[1]), "+f"(d[2]), "+f"(d[3])
        : "r"(a[0]), "r"(a[1]), "r"(a[2]), "r"(a[3]), "r"(b[0]), "r"(b[1]));
}

// ---------------------------------------------------------------------------
// tf32 tensor-core GEMM: out[M,N] = A[M,K] @ W[K,N] + bias. M=4096,N=K=1024
// CTA 128x128, K-tile 32, 8 warps (2x4), warp 64x32. smem holds tf32 bits.
// ---------------------------------------------------------------------------
template<int LAYOUT>
__global__ void __launch_bounds__(256, 2)
gemm_tf32_kernel(const float* __restrict__ A,
                 const float* __restrict__ W,
                 const float* __restrict__ bias,
                 float* __restrict__ out)
{
    __shared__ uint32_t As[128][36];
    __shared__ uint32_t Ws[32][136];

    const int tid  = threadIdx.x;
    const int lane = tid & 31;
    const int wid  = tid >> 5;
    const int warpM = wid & 1;
    const int warpN = wid >> 1;
    const int mbase = warpM * 64;
    const int nbase = warpN * 32;
    const int m0 = blockIdx.y * 128;
    const int n0 = blockIdx.x * 128;
    const int lr = lane >> 2;
    const int lc = lane & 3;

    float acc[4][4][4] = {};

    for (int kt = 0; kt < 32; kt++) {
        const int k0 = kt * 32;
        #pragma unroll
        for (int it = 0; it < 4; it++) {
            int ch = tid + it * 256;
            int r = ch >> 3, c4 = (ch & 7) * 4;
            float4 v = *(const float4*)(A + (size_t)(m0 + r) * Kdim + k0 + c4);
            uint4 u = make_uint4(f2tf(v.x), f2tf(v.y), f2tf(v.z), f2tf(v.w));
            *(uint4*)(&As[r][c4]) = u;
        }
        #pragma unroll
        for (int it = 0; it < 4; it++) {
            int ch = tid + it * 256;
            int r = ch >> 5, c4 = (ch & 31) * 4;
            float4 v = *(const float4*)(W + (size_t)(k0 + r) * 1024 + n0 + c4);
            uint4 u = make_uint4(f2tf(v.x), f2tf(v.y), f2tf(v.z), f2tf(v.w));
            *(uint4*)(&Ws[r][c4]) = u;
        }
        __syncthreads();

        #pragma unroll
        for (int ks = 0; ks < 4; ks++) {
            const int kc = ks * 8;
            uint32_t af[4][4];
            #pragma unroll
            for (int mf = 0; mf < 4; mf++) {
                const int r0 = mbase + mf * 16 + lr;
                const int c0 = kc + lc;
                af[mf][0] = As[r0][c0];
                af[mf][1] = As[r0 + 8][c0];
                af[mf][2] = As[r0][c0 + 4];
                af[mf][3] = As[r0 + 8][c0 + 4];
            }
            uint32_t bf[4][2];
            #pragma unroll
            for (int nf = 0; nf < 4; nf++) {
                const int nn = nbase + nf * 8 + lr;
                bf[nf][0] = Ws[kc + lc][nn];
                bf[nf][1] = Ws[kc + 4 + lc][nn];
            }
            #pragma unroll
            for (int mf = 0; mf < 4; mf++)
                #pragma unroll
                for (int nf = 0; nf < 4; nf++)
                    mma_tf32(acc[mf][nf], af[mf], bf[nf]);
        }
        __syncthreads();
    }

    #pragma unroll
    for (int mf = 0; mf < 4; mf++) {
        const int r0 = m0 + mbase + mf * 16 + lr;
        #pragma unroll
        for (int nf = 0; nf < 4; nf++) {
            const int n = n0 + nbase + nf * 8 + lc * 2;
            const float b0 = bias[n], b1 = bias[n + 1];
            float2 lo = make_float2(acc[mf][nf][0] + b0, acc[mf][nf][1] + b1);
            float2 hi = make_float2(acc[mf][nf][2] + b0, acc[mf][nf][3] + b1);
            if (LAYOUT == 0) {
                *(float2*)(out + (size_t)r0 * 1024 + n) = lo;
                *(float2*)(out + (size_t)(r0 + 8) * 1024 + n) = hi;
            } else {
                const int h = n >> 6, dk = n & 63;
                {
                    const int bb = r0 >> 11, l = r0 & 2047;
                    *(float2*)(out + (((size_t)(bb*Hdim + h) * Ldim) + l) * DKdim + dk) = lo;
                }
                {
                    const int m2 = r0 + 8;
                    const int bb = m2 >> 11, l = m2 & 2047;
                    *(float2*)(out + (((size_t)(bb*Hdim + h) * Ldim) + l) * DKdim + dk) = hi;
                }
            }
        }
    }
}

// ---------------------------------------------------------------------------
// Flash attention v2: CTA = 128 q rows, 8 warps, warp tile M16 x N64.
// S in registers through softmax; Q fragments in registers; smem tf32.
// Ks stride 68, Vs stride 72, Ps stride 68 (per-warp private).
// ---------------------------------------------------------------------------
#define KST 68
#define VST 72
#define PST 68
#define OFF_K 0
#define OFF_V (64*KST)                 // 4352
#define OFF_P (OFF_V + 64*VST)         // 8960
#define SMEM_WORDS (OFF_P + 128*PST)   // 8960 + 8704 = 17664
#define ASMEM_BYTES (SMEM_WORDS * 4)   // 70656

__global__ void __launch_bounds__(256, 2)
attn_kernel(const float* __restrict__ Qg,
            const float* __restrict__ Kg,
            const float* __restrict__ Vg,
            float* __restrict__ ctx)
{
    extern __shared__ uint32_t sm[];
    uint32_t* Ks = sm + OFF_K;                 // [64][KST]
    uint32_t* Vs = sm + OFF_V;                 // [64][VST]
    uint32_t* Ps = sm + OFF_P;                 // [128][PST] (per-warp 16-row slices)

    const int tid  = threadIdx.x;
    const int lane = tid & 31;
    const int wid  = tid >> 5;
    const int lr = lane >> 2;      // 0..7
    const int lc = lane & 3;       // 0..3
    const int qb = blockIdx.x * 128;
    const int h  = blockIdx.y;
    const int b  = blockIdx.z;
    const float scale = 0.125f;

    const size_t hoff = ((size_t)(b*Hdim + h)) * Ldim * DKdim;
    const float* Qh = Qg + hoff;
    const float* Kh = Kg + hoff;
    const float* Vh = Vg + hoff;

    // ---- Stage Q (scaled) into Ps region as raw floats, then extract frags ----
    #pragma unroll
    for (int it = 0; it < 8; it++) {
        int ch = tid + it * 256;               // 0..2047
        int r = ch >> 4, c4 = (ch & 15) * 4;
        float4 v = *(const float4*)(Qh + (size_t)(qb + r) * 64 + c4);
        uint32_t* dst = Ps + r * PST + c4;
        dst[0] = __float_as_uint(v.x * scale);
        dst[1] = __float_as_uint(v.y * scale);
        dst[2] = __float_as_uint(v.z * scale);
        dst[3] = __float_as_uint(v.w * scale);
    }
    __syncthreads();

    uint32_t qf[8][4];
    {
        const uint32_t* Qw = Ps + (wid * 16) * PST;
        #pragma unroll
        for (int kk = 0; kk < 8; kk++) {
            const int c0 = kk * 8 + lc;
            qf[kk][0] = f2tf(__uint_as_float(Qw[lr * PST + c0]));
            qf[kk][1] = f2tf(__uint_as_float(Qw[(lr + 8) * PST + c0]));
            qf[kk][2] = f2tf(__uint_as_float(Qw[lr * PST + c0 + 4]));
            qf[kk][3] = f2tf(__uint_as_float(Qw[(lr + 8) * PST + c0 + 4]));
        }
    }

    float acc[8][4] = {};
    float m0 = -1e30f, m1 = -1e30f;
    float l0 = 0.0f,  l1 = 0.0f;
    uint32_t* Pw = Ps + (wid * 16) * PST;      // per-warp private slice

    for (int j = 0; j < Ldim; j += 64) {
        __syncthreads();   // all warps done with prev K/V (and Q stage on iter 0)
        // ---- stage K, V as tf32 bits ----
        #pragma unroll
        for (int it = 0; it < 4; it++) {
            int ch = tid + it * 256;           // 0..1023
            int r = ch >> 4, c4 = (ch & 15) * 4;
            float4 kv = *(const float4*)(Kh + (size_t)(j + r) * 64 + c4);
            *(uint4*)(Ks + r * KST + c4) =
                make_uint4(f2tf(kv.x), f2tf(kv.y), f2tf(kv.z), f2tf(kv.w));
            float4 vv = *(const float4*)(Vh + (size_t)(j + r) * 64 + c4);
            *(uint4*)(Vs + r * VST + c4) =
                make_uint4(f2tf(vv.x), f2tf(vv.y), f2tf(vv.z), f2tf(vv.w));
        }
        __syncthreads();

        // ---- S = Q @ K^T : warp computes 16x64 in registers ----
        float s[8][4] = {};
        #pragma unroll
        for (int kk = 0; kk < 8; kk++) {
            const int c0 = kk * 8 + lc;
            #pragma unroll
            for (int nf = 0; nf < 8; nf++) {
                uint32_t bf[2];
                bf[0] = Ks[(nf * 8 + lr) * KST + c0];
                bf[1] = Ks[(nf * 8 + lr) * KST + c0 + 4];
                mma_tf32(s[nf], qf[kk], bf);
            }
        }

        // ---- online softmax fully in registers ----
        float pm0 = -1e30f, pm1 = -1e30f;
        #pragma unroll
        for (int nf = 0; nf < 8; nf++) {
            pm0 = fmaxf(pm0, fmaxf(s[nf][0], s[nf][1]));
            pm1 = fmaxf(pm1, fmaxf(s[nf][2], s[nf][3]));
        }
        pm0 = fmaxf(pm0, __shfl_xor_sync(0xffffffffu, pm0, 1));
        pm0 = fmaxf(pm0, __shfl_xor_sync(0xffffffffu, pm0, 2));
        pm1 = fmaxf(pm1, __shfl_xor_sync(0xffffffffu, pm1, 1));
        pm1 = fmaxf(pm1, __shfl_xor_sync(0xffffffffu, pm1, 2));
        const float mn0 = fmaxf(m0, pm0);
        const float mn1 = fmaxf(m1, pm1);
        const float corr0 = __expf(m0 - mn0);
        const float corr1 = __expf(m1 - mn1);
        float ps0 = 0.0f, ps1 = 0.0f;
        #pragma unroll
        for (int nf = 0; nf < 8; nf++) {
            s[nf][0] = __expf(s[nf][0] - mn0);
            s[nf][1] = __expf(s[nf][1] - mn0);
            s[nf][2] = __expf(s[nf][2] - mn1);
            s[nf][3] = __expf(s[nf][3] - mn1);
            ps0 += s[nf][0] + s[nf][1];
            ps1 += s[nf][2] + s[nf][3];
        }
        ps0 += __shfl_xor_sync(0xffffffffu, ps0, 1);
        ps0 += __shfl_xor_sync(0xffffffffu, ps0, 2);
        ps1 += __shfl_xor_sync(0xffffffffu, ps1, 1);
        ps1 += __shfl_xor_sync(0xffffffffu, ps1, 2);
        m0 = mn0; m1 = mn1;
        l0 = l0 * corr0 + ps0;
        l1 = l1 * corr1 + ps1;

        // rescale accumulator
        #pragma unroll
        for (int nf = 0; nf < 8; nf++) {
            acc[nf][0] *= corr0; acc[nf][1] *= corr0;
            acc[nf][2] *= corr1; acc[nf][3] *= corr1;
        }

        // ---- store P (tf32) to per-warp smem, then PV mma ----
        #pragma unroll
        for (int nf = 0; nf < 8; nf++) {
            const int col = nf * 8 + lc * 2;
            uint2 plo = make_uint2(f2tf(s[nf][0]), f2tf(s[nf][1]));
            uint2 phi = make_uint2(f2tf(s[nf][2]), f2tf(s[nf][3]));
            *(uint2*)(Pw + lr * PST + col)       = plo;
            *(uint2*)(Pw + (lr + 8) * PST + col) = phi;
        }
        __syncwarp();

        #pragma unroll
        for (int kk = 0; kk < 8; kk++) {
            const int c0 = kk * 8 + lc;
            uint32_t pf[4];
            pf[0] = Pw[lr * PST + c0];
            pf[1] = Pw[(lr + 8) * PST + c0];
            pf[2] = Pw[lr * PST + c0 + 4];
            pf[3] = Pw[(lr + 8) * PST + c0 + 4];
            #pragma unroll
            for (int nf = 0; nf < 8; nf++) {
                uint32_t vf[2];
                vf[0] = Vs[(kk * 8 + lc) * VST + nf * 8 + lr];
                vf[1] = Vs[(kk * 8 + 4 + lc) * VST + nf * 8 + lr];
                mma_tf32(acc[nf], pf, vf);
            }
        }
        __syncwarp();   // P reads done before next iteration's P stores
    }

    // ---- epilogue: normalize, write ctx[b, l, h*64 + d] ----
    const float inv0 = 1.0f / l0;
    const float inv1 = 1.0f / l1;
    #pragma unroll
    for (int nf = 0; nf < 8; nf++) {
        const int col = h * 64 + nf * 8 + lc * 2;
        {
            const int l = qb + wid * 16 + lr;
            float2 o = make_float2(acc[nf][0] * inv0, acc[nf][1] * inv0);
            *(float2*)(ctx + ((size_t)b * Ldim + l) * INNERdim + col) = o;
        }
        {
            const int l = qb + wid * 16 + lr + 8;
            float2 o = make_float2(acc[nf][2] * inv1, acc[nf][3] * inv1);
            *(float2*)(ctx + ((size_t)b * Ldim + l) * INNERdim + col) = o;
        }
    }
}

// ---------------------------------------------------------------------------
extern "C" void kernel_launch(void* const* d_in, const int* in_sizes, int n_in,
                              void* d_out, int out_size)
{
    const float* x   = (const float*)d_in[0];
    const float* w_q = (const float*)d_in[1];
    const float* b_q = (const float*)d_in[2];
    const float* w_k = (const float*)d_in[3];
    const float* b_k = (const float*)d_in[4];
    const float* w_v = (const float*)d_in[5];
    const float* b_v = (const float*)d_in[6];
    const float* w_o = (const float*)d_in[7];
    const float* b_o = (const float*)d_in[8];

    float *gq, *gk, *gv, *gctx;
    cudaGetSymbolAddress((void**)&gq,   g_q);
    cudaGetSymbolAddress((void**)&gk,   g_k);
    cudaGetSymbolAddress((void**)&gv,   g_v);
    cudaGetSymbolAddress((void**)&gctx, g_ctx);

    cudaFuncSetAttribute(attn_kernel,
                         cudaFuncAttributeMaxDynamicSharedMemorySize, ASMEM_BYTES);

    dim3 blk(256);
    dim3 gg(INNERdim/128, Mdim/128);   // (8, 32)

    gemm_tf32_kernel<1><<<gg, blk>>>(x, w_q, b_q, gq);
    gemm_tf32_kernel<1><<<gg, blk>>>(x, w_k, b_k, gk);
    gemm_tf32_kernel<1><<<gg, blk>>>(x, w_v, b_v, gv);

    dim3 ga(Ldim/128, Hdim, Bdim);     // (16, 16, 2)
    attn_kernel<<<ga, blk, ASMEM_BYTES>>>(gq, gk, gv, gctx);

    gemm_tf32_kernel<0><<<gg, blk>>>(gctx, w_o, b_o, (float*)d_out);
}